// round 1
// baseline (speedup 1.0000x reference)
#include <cuda_runtime.h>

#define DSZ   64
#define NA    (DSZ*DSZ*DSZ)     // 262144 anchors
#define NDIR  64
#define NBIN  65                // NUM_STEPS + 1

// dh = 2*sqrt(3); (h - min_h)/dh = h/dh + 32 exactly (min_h = -sqrt(3)*64)
#define INV_DH 0.28867513459481287f

// Scratch (no allocation allowed in kernel_launch)
__device__ float g_vals[NA * 8];        // 8 pre-signed values per anchor (8 MB)
__device__ float g_hist[NDIR * NBIN];   // per-direction signed bin histogram

// ---------------------------------------------------------------------------
// Pass 1: precompute the 8 signed cell values per anchor (direction-independent)
//   slot 0: +x                      (vertex)
//   slot 1: -max over i-pair        (edge x)
//   slot 2: -max over j-pair        (edge y)
//   slot 3: -max over l-pair        (edge z)
//   slot 4: +max over (j,l) 2x2     (face yz)
//   slot 5: +max over (i,l) 2x2     (face xz)
//   slot 6: +max over (i,j) 2x2     (face xy)
//   slot 7: -max over 2x2x2         (cube)
// ---------------------------------------------------------------------------
__global__ void prep_kernel(const float* __restrict__ x) {
    int a = blockIdx.x * blockDim.x + threadIdx.x;
    if (a >= NA) return;
    int i = a >> 12, j = (a >> 6) & 63, l = a & 63;
    bool bi = i < 63, bj = j < 63, bl = l < 63;

    float x000 = x[a];
    float x001 = bl ? x[a + 1] : 0.f;
    float x010 = bj ? x[a + 64] : 0.f;
    float x011 = (bj && bl) ? x[a + 65] : 0.f;
    float x100 = bi ? x[a + 4096] : 0.f;
    float x101 = (bi && bl) ? x[a + 4097] : 0.f;
    float x110 = (bi && bj) ? x[a + 4160] : 0.f;
    float x111 = (bi && bj && bl) ? x[a + 4161] : 0.f;

    float4 A, B;
    A.x = x000;
    A.y = bi ? -fmaxf(x000, x100) : 0.f;
    A.z = bj ? -fmaxf(x000, x010) : 0.f;
    A.w = bl ? -fmaxf(x000, x001) : 0.f;
    B.x = (bj && bl) ? fmaxf(fmaxf(x000, x001), fmaxf(x010, x011)) : 0.f;
    B.y = (bi && bl) ? fmaxf(fmaxf(x000, x001), fmaxf(x100, x101)) : 0.f;
    B.z = (bi && bj) ? fmaxf(fmaxf(x000, x010), fmaxf(x100, x110)) : 0.f;
    B.w = (bi && bj && bl)
        ? -fmaxf(fmaxf(fmaxf(x000, x001), fmaxf(x010, x011)),
                 fmaxf(fmaxf(x100, x101), fmaxf(x110, x111)))
        : 0.f;

    float4* out = reinterpret_cast<float4*>(g_vals);
    out[2 * a]     = A;
    out[2 * a + 1] = B;
}

__global__ void zero_hist() {
    int t = blockIdx.x * blockDim.x + threadIdx.x;
    if (t < NDIR * NBIN) g_hist[t] = 0.f;
}

// ---------------------------------------------------------------------------
// Pass 2: per-direction signed histogram. Grid (16, 64): blockIdx.y = direction,
// 16 blocks x 256 threads = 4096 threads = one (j,l) slice; each thread walks i.
// Per-warp replicated shared histograms kill cross-warp atomic contention.
// ---------------------------------------------------------------------------
__global__ void __launch_bounds__(256) main_kernel(const float* __restrict__ dirs) {
    const int k = blockIdx.y;
    const float d0 = dirs[3 * k], d1 = dirs[3 * k + 1], d2 = dirs[3 * k + 2];
    const float p0 = fmaxf(d0, 0.f), p1 = fmaxf(d1, 0.f), p2 = fmaxf(d2, 0.f);
    const float q1 = p0 * INV_DH, q2 = p1 * INV_DH, q3 = p2 * INV_DH;
    const float q4 = (p1 + p2) * INV_DH, q5 = (p0 + p2) * INV_DH;
    const float q6 = (p0 + p1) * INV_DH, q7 = (p0 + p1 + p2) * INV_DH;

    __shared__ float sh[8][NBIN + 1];   // per-warp replicas, padded
    const int tid = threadIdx.x, w = tid >> 5;
    for (int t = tid; t < 8 * (NBIN + 1); t += 256) ((float*)sh)[t] = 0.f;
    __syncthreads();

    const int base = blockIdx.x * 256 + tid;     // 0..4095 => fixed (j,l)
    const int j = base >> 6, l = base & 63;
    const float hb = fmaf(d1, (float)j, d2 * (float)l);
    const float4* __restrict__ vp = reinterpret_cast<const float4*>(g_vals);

    #pragma unroll 4
    for (int i = 0; i < 64; i++) {
        float h  = fmaf(d0, (float)i, hb);
        float f  = fmaf(h, INV_DH, 32.0f);   // (h - min_h)/dh
        float bf = ceilf(f);
        float g  = bf - f;                   // exact (|bf-f| < 1)
        int   b  = (int)bf;

        int anchor = (i << 12) + base;
        float4 A = vp[2 * anchor];
        float4 B = vp[2 * anchor + 1];

        float T  = ((A.x + A.y) + (A.z + A.w)) + ((B.x + B.y) + (B.z + B.w));
        float S1 = 0.f;
        S1 += (q1 > g) ? A.y : 0.f;
        S1 += (q2 > g) ? A.z : 0.f;
        S1 += (q3 > g) ? A.w : 0.f;
        S1 += (q4 > g) ? B.x : 0.f;
        S1 += (q5 > g) ? B.y : 0.f;
        S1 += (q6 > g) ? B.z : 0.f;
        S1 += (q7 > g) ? B.w : 0.f;
        float S0 = T - S1;

        if ((unsigned)b <= 64u)       atomicAdd(&sh[w][b],     S0);
        if ((unsigned)(b + 1) <= 64u) atomicAdd(&sh[w][b + 1], S1);
    }
    __syncthreads();

    for (int bin = tid; bin < NBIN; bin += 256) {
        float s = 0.f;
        #pragma unroll
        for (int r = 0; r < 8; r++) s += sh[r][bin];
        atomicAdd(&g_hist[k * NBIN + bin], s);
    }
}

// ---------------------------------------------------------------------------
// Pass 3: cumulative sum over bins -> output (64, 65)
// ---------------------------------------------------------------------------
__global__ void finalize(float* __restrict__ out) {
    int k = blockIdx.x;
    int s = threadIdx.x;
    if (s >= NBIN) return;
    float acc = 0.f;
    for (int b = 0; b <= s; b++) acc += g_hist[k * NBIN + b];
    out[k * NBIN + s] = acc;
}

extern "C" void kernel_launch(void* const* d_in, const int* in_sizes, int n_in,
                              void* d_out, int out_size) {
    const float* x    = (const float*)d_in[0];
    const float* dirs = (const float*)d_in[1];
    float* out = (float*)d_out;

    prep_kernel<<<NA / 256, 256>>>(x);
    zero_hist<<<(NDIR * NBIN + 255) / 256, 256>>>();
    main_kernel<<<dim3(16, NDIR), 256>>>(dirs);
    finalize<<<NDIR, 96>>>(out);
}

// round 2
// speedup vs baseline: 1.7817x; 1.7817x over previous
#include <cuda_runtime.h>

#define NDIR  64
#define NBIN  65                 // NUM_STEPS + 1
#define INV_DH 0.28867513459481287f   // 1/(2*sqrt(3)); (h-min_h)/dh = h/dh + 32
#define D_PER 4                  // directions per pass
#define NGRP  (NDIR / D_PER)     // 16
#define TPB   128
#define NTILE 32                 // 4096 (j,l) pairs / 128 threads

__device__ float g_hist[NDIR * NBIN];

__global__ void zero_hist() {
    int t = blockIdx.x * blockDim.x + threadIdx.x;
    if (t < NDIR * NBIN) g_hist[t] = 0.f;
}

// ---------------------------------------------------------------------------
// Fused kernel: each thread owns one (j,l) column, walks i (step = d0 per dir).
// Cell values computed on the fly from an 8-voxel register stencil.
// Bin index is slowly varying along i -> run-length accumulate in registers,
// flush to shared hist only on bin change (~10 atomics/thread vs 128).
// ---------------------------------------------------------------------------
__global__ void __launch_bounds__(TPB) main_kernel(const float* __restrict__ x,
                                                   const float* __restrict__ dirs) {
    const int g   = blockIdx.y;            // direction group (D_PER dirs)
    const int tid = threadIdx.x;
    __shared__ float sh[D_PER][NBIN + 2];  // bins 0..65 (65 = overflow slot, dropped)

    for (int t = tid; t < D_PER * (NBIN + 2); t += TPB) ((float*)sh)[t] = 0.f;
    __syncthreads();

    const int base = blockIdx.x * TPB + tid;   // 0..4095
    const int j = base >> 6, l = base & 63;
    const bool bj = j < 63, bl = l < 63;

    // Per-direction constants
    float stepf[D_PER], basef[D_PER];
    float q1[D_PER], q2[D_PER], q3[D_PER], q4[D_PER], q5[D_PER], q6[D_PER], q7[D_PER];
    #pragma unroll
    for (int d = 0; d < D_PER; d++) {
        int k = g * D_PER + d;
        float d0 = dirs[3*k], d1 = dirs[3*k+1], d2 = dirs[3*k+2];
        float p0 = fmaxf(d0, 0.f), p1 = fmaxf(d1, 0.f), p2 = fmaxf(d2, 0.f);
        q1[d] = p0 * INV_DH;            // edge along i
        q2[d] = p1 * INV_DH;            // edge along j
        q3[d] = p2 * INV_DH;            // edge along l
        q4[d] = (p1 + p2) * INV_DH;     // face spanning (j,l)
        q5[d] = (p0 + p2) * INV_DH;     // face spanning (i,l)
        q6[d] = (p0 + p1) * INV_DH;     // face spanning (i,j)
        q7[d] = (p0 + p1 + p2) * INV_DH;// cube
        stepf[d] = d0 * INV_DH;
        basef[d] = fmaf(d1 * INV_DH, (float)j, fmaf(d2 * INV_DH, (float)l, 32.0f));
    }

    int   cur[D_PER];
    float acc0[D_PER], acc1[D_PER];
    #pragma unroll
    for (int d = 0; d < D_PER; d++) {
        cur[d]  = (int)ceilf(basef[d]);   // bin at i = 0
        acc0[d] = 0.f;
        acc1[d] = 0.f;
    }

    // Stencil registers for plane i (c) and i+1 (n)
    int idx = j * 64 + l;
    float c00 = x[idx];
    float c01 = bl ? x[idx + 1]  : 0.f;
    float c10 = bj ? x[idx + 64] : 0.f;
    float c11 = (bj && bl) ? x[idx + 65] : 0.f;

    for (int i = 0; i < 64; i++) {
        const bool bi = i < 63;
        const int nidx = idx + 4096;
        float n00 = bi ? x[nidx] : 0.f;
        float n01 = (bi && bl) ? x[nidx + 1]  : 0.f;
        float n10 = (bi && bj) ? x[nidx + 64] : 0.f;
        float n11 = (bi && bj && bl) ? x[nidx + 65] : 0.f;

        // 8 signed cell values (direction-independent)
        float m_i = fmaxf(c00, n00);
        float mjl = fmaxf(fmaxf(c00, c01), fmaxf(c10, c11));
        float v_ei  = bi ? -m_i : 0.f;
        float v_ej  = bj ? -fmaxf(c00, c10) : 0.f;
        float v_el  = bl ? -fmaxf(c00, c01) : 0.f;
        float v_fjl = (bj && bl) ? mjl : 0.f;
        float v_fil = (bi && bl) ? fmaxf(m_i, fmaxf(c01, n01)) : 0.f;
        float v_fij = (bi && bj) ? fmaxf(m_i, fmaxf(c10, n10)) : 0.f;
        float v_c   = (bi && bj && bl)
            ? -fmaxf(mjl, fmaxf(fmaxf(n00, n01), fmaxf(n10, n11))) : 0.f;

        float T  = ((c00 + v_ei) + (v_ej + v_el)) + ((v_fjl + v_fil) + (v_fij + v_c));
        float fi = (float)i;

        #pragma unroll
        for (int d = 0; d < D_PER; d++) {
            float f  = fmaf(stepf[d], fi, basef[d]);
            float bf = ceilf(f);
            float gg = bf - f;                  // exact
            int   b  = (int)bf;                 // in [1, 64]
            float S1 = 0.f;
            S1 += (q1[d] > gg) ? v_ei  : 0.f;
            S1 += (q2[d] > gg) ? v_ej  : 0.f;
            S1 += (q3[d] > gg) ? v_el  : 0.f;
            S1 += (q4[d] > gg) ? v_fjl : 0.f;
            S1 += (q5[d] > gg) ? v_fil : 0.f;
            S1 += (q6[d] > gg) ? v_fij : 0.f;
            S1 += (q7[d] > gg) ? v_c   : 0.f;
            float S0 = T - S1;

            if (b != cur[d]) {                  // rare: bin moved
                atomicAdd(&sh[d][cur[d]], acc0[d]);
                if (b != cur[d] + 1) {          // jumped by >1 (or backwards)
                    atomicAdd(&sh[d][cur[d] + 1], acc1[d]);
                    acc1[d] = 0.f;
                }
                acc0[d] = acc1[d];              // adjacent: old b+1 acc becomes new b acc
                acc1[d] = 0.f;
                cur[d]  = b;
            }
            acc0[d] += S0;
            acc1[d] += S1;
        }

        c00 = n00; c01 = n01; c10 = n10; c11 = n11;
        idx = nidx;
    }

    // Final flush
    #pragma unroll
    for (int d = 0; d < D_PER; d++) {
        atomicAdd(&sh[d][cur[d]],     acc0[d]);
        atomicAdd(&sh[d][cur[d] + 1], acc1[d]);
    }
    __syncthreads();

    // Reduce block hist to global (drop overflow slot 65)
    for (int t = tid; t < D_PER * NBIN; t += TPB) {
        int d = t / NBIN, bin = t % NBIN;
        float v = sh[d][bin];
        if (v != 0.f) atomicAdd(&g_hist[(g * D_PER + d) * NBIN + bin], v);
    }
}

// ---------------------------------------------------------------------------
// Cumulative sum over bins -> output (64, 65)
// ---------------------------------------------------------------------------
__global__ void finalize(float* __restrict__ out) {
    int k = blockIdx.x;
    int s = threadIdx.x;
    if (s >= NBIN) return;
    float acc = 0.f;
    for (int b = 0; b <= s; b++) acc += g_hist[k * NBIN + b];
    out[k * NBIN + s] = acc;
}

extern "C" void kernel_launch(void* const* d_in, const int* in_sizes, int n_in,
                              void* d_out, int out_size) {
    const float* x    = (const float*)d_in[0];
    const float* dirs = (const float*)d_in[1];
    float* out = (float*)d_out;

    zero_hist<<<(NDIR * NBIN + 255) / 256, 256>>>();
    main_kernel<<<dim3(NTILE, NGRP), TPB>>>(x, dirs);
    finalize<<<NDIR, 96>>>(out);
}

// round 3
// speedup vs baseline: 2.8708x; 1.6112x over previous
#include <cuda_runtime.h>

#define NDIR   64
#define NBIN   65                      // NUM_STEPS + 1
#define INV_DH 0.28867513459481287f    // 1/(2*sqrt(3))
#define D_PER  4
#define NGRP   (NDIR / D_PER)          // 16
#define TPB    128
#define NTILE  32                      // 4096 (j,l) columns / 128 threads
#define ISEG   4                       // i split into 4 segments of 16
#define ILEN   16
#define NSLOT  (NTILE * ISEG)          // 128 partials per direction
#define SBIN   66                      // bins 0..65 (65 never hit, kept for uniformity)

// Non-atomic partial histograms: [dir][slot][SBIN]
__device__ float g_part[NDIR * NSLOT * SBIN];

// Predicated shared-memory reduction: @p red.shared — no BSSY/BSYNC branch.
__device__ __forceinline__ void red_sh_pred(unsigned addr, float v, int pred) {
    asm volatile("{ .reg .pred p; setp.ne.s32 p, %2, 0;\n\t"
                 "@p red.shared.add.f32 [%0], %1; }"
                 :: "r"(addr), "f"(v), "r"(pred) : "memory");
}
__device__ __forceinline__ void red_sh(unsigned addr, float v) {
    asm volatile("red.shared.add.f32 [%0], %1;" :: "r"(addr), "f"(v) : "memory");
}
// Predicated accumulate: acc += (q > g) ? v : 0 in 2 instrs (FSETP + @P FADD)
#define PADD(acc, qv, gv, vv) \
    asm("{ .reg .pred p; setp.gt.f32 p, %1, %2;\n\t" \
        "@p add.f32 %0, %0, %3; }" : "+f"(acc) : "f"(qv), "f"(gv), "f"(vv))

__global__ void __launch_bounds__(TPB) main_kernel(const float* __restrict__ x,
                                                   const float* __restrict__ dirs) {
    const int g   = blockIdx.z;                 // direction group
    const int seg = blockIdx.y;                 // i segment
    const int tid = threadIdx.x;
    __shared__ float sh[D_PER][SBIN + 2];       // padded rows

    for (int t = tid; t < D_PER * (SBIN + 2); t += TPB) ((float*)sh)[t] = 0.f;
    __syncthreads();

    const int base = blockIdx.x * TPB + tid;    // (j,l) column id, 0..4095
    const int j = base >> 6, l = base & 63;
    const float mj = (j < 63) ? 1.f : 0.f;
    const float ml = (l < 63) ? 1.f : 0.f;
    const float mjl = mj * ml;
    const int i0 = seg * ILEN;

    float stepf[D_PER], f0[D_PER];
    float q1[D_PER], q2[D_PER], q3[D_PER], q4[D_PER], q5[D_PER], q6[D_PER], q7[D_PER];
    int prevb[D_PER];
    float acc0[D_PER], acc1[D_PER];
    unsigned row[D_PER];
    #pragma unroll
    for (int d = 0; d < D_PER; d++) {
        int k = g * D_PER + d;
        float d0 = dirs[3*k], d1 = dirs[3*k+1], d2 = dirs[3*k+2];
        float p0 = fmaxf(d0, 0.f), p1 = fmaxf(d1, 0.f), p2 = fmaxf(d2, 0.f);
        q1[d] = p0 * INV_DH;   q2[d] = p1 * INV_DH;   q3[d] = p2 * INV_DH;
        q4[d] = (p1 + p2) * INV_DH;  q5[d] = (p0 + p2) * INV_DH;
        q6[d] = (p0 + p1) * INV_DH;  q7[d] = (p0 + p1 + p2) * INV_DH;
        stepf[d] = d0 * INV_DH;
        float b0 = fmaf(d1 * INV_DH, (float)j, fmaf(d2 * INV_DH, (float)l, 32.0f));
        f0[d] = fmaf(stepf[d], (float)i0, b0);
        prevb[d] = (int)ceilf(f0[d]);
        acc0[d] = 0.f; acc1[d] = 0.f;
        row[d] = (unsigned)__cvta_generic_to_shared(&sh[d][0]);
    }

    // Stencil planes: c = plane i, n = plane i+1 (boundary-masked at load)
    int idx = i0 * 4096 + base;
    float c00 = x[idx];
    float c01 = (l < 63) ? x[idx + 1]  : 0.f;
    float c10 = (j < 63) ? x[idx + 64] : 0.f;
    float c11 = (j < 63 && l < 63) ? x[idx + 65] : 0.f;

    #pragma unroll 4
    for (int ii = 0; ii < ILEN; ii++) {
        const int i = i0 + ii;
        const float mi = (i < 63) ? 1.f : 0.f;
        const int nidx = idx + 4096;
        float n00 = (i < 63) ? x[nidx] : 0.f;
        float n01 = (i < 63 && l < 63) ? x[nidx + 1]  : 0.f;
        float n10 = (i < 63 && j < 63) ? x[nidx + 64] : 0.f;
        float n11 = (i < 63 && j < 63 && l < 63) ? x[nidx + 65] : 0.f;

        // 8 signed cell values (mask-multiplied — no branches)
        float m_i   = fmaxf(c00, n00);
        float mc    = fmaxf(fmaxf(c00, c01), fmaxf(c10, c11));
        float v_ei  = -m_i * mi;
        float v_ej  = -fmaxf(c00, c10) * mj;
        float v_el  = -fmaxf(c00, c01) * ml;
        float v_fjl = mc * mjl;
        float v_fil = fmaxf(m_i, fmaxf(c01, n01)) * (mi * ml);
        float v_fij = fmaxf(m_i, fmaxf(c10, n10)) * (mi * mj);
        float v_c   = -fmaxf(mc, fmaxf(fmaxf(n00, n01), fmaxf(n10, n11))) * (mi * mjl);
        float T = ((c00 + v_ei) + (v_ej + v_el)) + ((v_fjl + v_fil) + (v_fij + v_c));
        float fi = (float)ii;

        #pragma unroll
        for (int d = 0; d < D_PER; d++) {
            float f  = fmaf(stepf[d], fi, f0[d]);
            float bf = ceilf(f);
            float gg = bf - f;
            int   b  = (int)bf;

            float S1a = 0.f, S1b = 0.f;
            PADD(S1a, q1[d], gg, v_ei);
            PADD(S1b, q2[d], gg, v_ej);
            PADD(S1a, q3[d], gg, v_el);
            PADD(S1b, q4[d], gg, v_fjl);
            PADD(S1a, q5[d], gg, v_fil);
            PADD(S1b, q6[d], gg, v_fij);
            PADD(S1a, q7[d], gg, v_c);
            float S1 = S1a + S1b;

            // Branch-free run flush (|b - prevb| <= 1 guaranteed)
            int up = (b > prevb[d]);
            int dn = (b < prevb[d]);
            red_sh_pred(row[d] + (unsigned)prevb[d] * 4u,      acc0[d], up);
            red_sh_pred(row[d] + (unsigned)(prevb[d] + 1) * 4u, acc1[d], dn);
            float na0 = up ? acc1[d] : (dn ? 0.f : acc0[d]);
            float na1 = dn ? acc0[d] : (up ? 0.f : acc1[d]);
            acc0[d] = na0 + (T - S1);
            acc1[d] = na1 + S1;
            prevb[d] = b;
        }

        c00 = n00; c01 = n01; c10 = n10; c11 = n11;
        idx = nidx;
    }

    // Final flush
    #pragma unroll
    for (int d = 0; d < D_PER; d++) {
        red_sh(row[d] + (unsigned)prevb[d] * 4u,       acc0[d]);
        red_sh(row[d] + (unsigned)(prevb[d] + 1) * 4u, acc1[d]);
    }
    __syncthreads();

    // Non-atomic partial write: slot = tile*ISEG + seg
    const int slot = blockIdx.x * ISEG + seg;
    for (int t = tid; t < D_PER * SBIN; t += TPB) {
        int d = t / SBIN, bin = t - d * SBIN;
        int k = g * D_PER + d;
        g_part[(k * NSLOT + slot) * SBIN + bin] = sh[d][bin];
    }
}

// Reduce 128 partials per direction, then inclusive prefix over bins.
__global__ void __launch_bounds__(128) finalize(float* __restrict__ out) {
    const int k = blockIdx.x;
    const int s = threadIdx.x;
    __shared__ float bins[NBIN];
    if (s < NBIN) {
        float acc = 0.f;
        const float* p = &g_part[k * NSLOT * SBIN + s];
        #pragma unroll 8
        for (int slot = 0; slot < NSLOT; slot++) acc += p[slot * SBIN];
        bins[s] = acc;
    }
    __syncthreads();
    if (s < NBIN) {
        float acc = 0.f;
        for (int b = 0; b <= s; b++) acc += bins[b];
        out[k * NBIN + s] = acc;
    }
}

extern "C" void kernel_launch(void* const* d_in, const int* in_sizes, int n_in,
                              void* d_out, int out_size) {
    const float* x    = (const float*)d_in[0];
    const float* dirs = (const float*)d_in[1];
    float* out = (float*)d_out;

    main_kernel<<<dim3(NTILE, ISEG, NGRP), TPB>>>(x, dirs);
    finalize<<<NDIR, 128>>>(out);
}

// round 4
// speedup vs baseline: 3.2926x; 1.1469x over previous
#include <cuda_runtime.h>

#define NDIR   64
#define NBIN   65                      // NUM_STEPS + 1
#define INV_DH 0.28867513459481287f    // 1/(2*sqrt(3))
#define D_PER  4
#define NGRP   (NDIR / D_PER)          // 16
#define TPB    128
#define NTILE  32                      // 4096 (j,l) columns / 128 threads
#define ISEG   4                       // i split into 4 segments of 16
#define ILEN   16
#define NSLOT  (NTILE * ISEG)          // 128 partials per direction
#define SBIN   66                      // bins 0..65
#define NX     262144                  // 64^3
#define XPAD   4224                    // covers +4096+65 overreach
#define NXP    (NX + XPAD)

__device__ float g_part[NDIR * NSLOT * SBIN];
__device__ float g_xp[NXP];            // padded copy of x (pad = 0, finite)

__global__ void pad_kernel(const float* __restrict__ x) {
    int t = blockIdx.x * blockDim.x + threadIdx.x;
    if (t < NXP) g_xp[t] = (t < NX) ? x[t] : 0.f;
}

// Predicated shared red: setp inside asm (no bool materialization, no BSSY)
#define RED_IF_GT(addr, v, a, b) \
    asm volatile("{ .reg .pred p; setp.gt.s32 p, %2, %3;\n\t" \
                 "@p red.shared.add.f32 [%0], %1; }" \
                 :: "r"(addr), "f"(v), "r"(a), "r"(b) : "memory")
#define RED_IF_LT(addr, v, a, b) \
    asm volatile("{ .reg .pred p; setp.lt.s32 p, %2, %3;\n\t" \
                 "@p red.shared.add.f32 [%0], %1; }" \
                 :: "r"(addr), "f"(v), "r"(a), "r"(b) : "memory")

__device__ __forceinline__ void red_sh(unsigned addr, float v) {
    asm volatile("red.shared.add.f32 [%0], %1;" :: "r"(addr), "f"(v) : "memory");
}

__global__ void __launch_bounds__(TPB) main_kernel(const float* __restrict__ dirs) {
    const int g   = blockIdx.z;
    const int seg = blockIdx.y;
    const int tid = threadIdx.x;
    __shared__ float sh[D_PER][SBIN + 2];

    for (int t = tid; t < D_PER * (SBIN + 2); t += TPB) ((float*)sh)[t] = 0.f;
    __syncthreads();

    const int base = blockIdx.x * TPB + tid;    // (j,l) column, 0..4095
    const int j = base >> 6, l = base & 63;
    const float mj = (j < 63) ? 1.f : 0.f;
    const float ml = (l < 63) ? 1.f : 0.f;
    const float mjl = mj * ml;
    const int i0 = seg * ILEN;

    float stepf[D_PER], f0[D_PER];
    float q1[D_PER], q2[D_PER], q3[D_PER], q4[D_PER], q5[D_PER], q6[D_PER], q7[D_PER];
    int prevb[D_PER];
    float acc0[D_PER], acc1[D_PER];
    unsigned row[D_PER];
    #pragma unroll
    for (int d = 0; d < D_PER; d++) {
        int k = g * D_PER + d;
        float d0 = dirs[3*k], d1 = dirs[3*k+1], d2 = dirs[3*k+2];
        float p0 = fmaxf(d0, 0.f), p1 = fmaxf(d1, 0.f), p2 = fmaxf(d2, 0.f);
        q1[d] = p0 * INV_DH;   q2[d] = p1 * INV_DH;   q3[d] = p2 * INV_DH;
        q4[d] = (p1 + p2) * INV_DH;  q5[d] = (p0 + p2) * INV_DH;
        q6[d] = (p0 + p1) * INV_DH;  q7[d] = (p0 + p1 + p2) * INV_DH;
        stepf[d] = d0 * INV_DH;
        float b0 = fmaf(d1 * INV_DH, (float)j, fmaf(d2 * INV_DH, (float)l, 32.0f));
        f0[d] = fmaf(stepf[d], (float)i0, b0);
        prevb[d] = (int)ceilf(f0[d]);
        acc0[d] = 0.f; acc1[d] = 0.f;
        row[d] = (unsigned)__cvta_generic_to_shared(&sh[d][0]);
    }

    // Unconditional stencil loads from the padded array (masks applied to values)
    int idx = i0 * 4096 + base;
    float c00 = g_xp[idx];
    float c01 = g_xp[idx + 1];
    float c10 = g_xp[idx + 64];
    float c11 = g_xp[idx + 65];

    #pragma unroll 4
    for (int ii = 0; ii < ILEN; ii++) {
        const float mi = ((i0 + ii) < 63) ? 1.f : 0.f;
        const int nidx = idx + 4096;
        float n00 = g_xp[nidx];
        float n01 = g_xp[nidx + 1];
        float n10 = g_xp[nidx + 64];
        float n11 = g_xp[nidx + 65];

        float m_i   = fmaxf(c00, n00);
        float mc    = fmaxf(fmaxf(c00, c01), fmaxf(c10, c11));
        float v_ei  = -m_i * mi;
        float v_ej  = -fmaxf(c00, c10) * mj;
        float v_el  = -fmaxf(c00, c01) * ml;
        float v_fjl = mc * mjl;
        float v_fil = fmaxf(m_i, fmaxf(c01, n01)) * (mi * ml);
        float v_fij = fmaxf(m_i, fmaxf(c10, n10)) * (mi * mj);
        float v_c   = -fmaxf(mc, fmaxf(fmaxf(n00, n01), fmaxf(n10, n11))) * (mi * mjl);
        float T = ((c00 + v_ei) + (v_ej + v_el)) + ((v_fjl + v_fil) + (v_fij + v_c));
        float fi = (float)ii;

        #pragma unroll
        for (int d = 0; d < D_PER; d++) {
            float f  = fmaf(stepf[d], fi, f0[d]);
            float bf = ceilf(f);
            float gg = bf - f;
            int   b  = (int)bf;                    // in [1, 64]

            // Select-based accumulation (FSETP+FSEL+FADD, 4-cyc deps), 2 chains
            float S1a = (q1[d] > gg) ? v_ei  : 0.f;
            float S1b = (q2[d] > gg) ? v_ej  : 0.f;
            S1a += (q3[d] > gg) ? v_el  : 0.f;
            S1b += (q4[d] > gg) ? v_fjl : 0.f;
            S1a += (q5[d] > gg) ? v_fil : 0.f;
            S1b += (q6[d] > gg) ? v_fij : 0.f;
            S1a += (q7[d] > gg) ? v_c   : 0.f;
            float S1 = S1a + S1b;

            // Branch-free run flush (|b - prevb| <= 1 guaranteed)
            RED_IF_GT(row[d] + (unsigned)prevb[d] * 4u,       acc0[d], b, prevb[d]);
            RED_IF_LT(row[d] + (unsigned)(prevb[d] + 1) * 4u, acc1[d], b, prevb[d]);
            int up = (b > prevb[d]);
            int dn = (b < prevb[d]);
            float na0 = up ? acc1[d] : (dn ? 0.f : acc0[d]);
            float na1 = dn ? acc0[d] : (up ? 0.f : acc1[d]);
            acc0[d] = na0 + (T - S1);
            acc1[d] = na1 + S1;
            prevb[d] = b;
        }

        c00 = n00; c01 = n01; c10 = n10; c11 = n11;
        idx = nidx;
    }

    #pragma unroll
    for (int d = 0; d < D_PER; d++) {
        red_sh(row[d] + (unsigned)prevb[d] * 4u,       acc0[d]);
        red_sh(row[d] + (unsigned)(prevb[d] + 1) * 4u, acc1[d]);
    }
    __syncthreads();

    const int slot = blockIdx.x * ISEG + seg;
    for (int t = tid; t < D_PER * SBIN; t += TPB) {
        int d = t / SBIN, bin = t - d * SBIN;
        int k = g * D_PER + d;
        g_part[(k * NSLOT + slot) * SBIN + bin] = sh[d][bin];
    }
}

// One block per direction; 8 groups of 65 threads each reduce 16 slots
// (coalesced 260B reads), tree-reduce in shared, then prefix sum.
__global__ void __launch_bounds__(520) finalize(float* __restrict__ out) {
    const int k   = blockIdx.x;
    const int tid = threadIdx.x;
    const int sub = tid / NBIN;          // 0..7
    const int bin = tid - sub * NBIN;    // 0..64
    __shared__ float red[8][NBIN];

    float acc = 0.f;
    const float* p = &g_part[k * NSLOT * SBIN + bin];
    #pragma unroll
    for (int s = 0; s < NSLOT / 8; s++)
        acc += p[(sub * (NSLOT / 8) + s) * SBIN];
    red[sub][bin] = acc;
    __syncthreads();

    if (sub == 0) {
        float t = 0.f;
        #pragma unroll
        for (int r = 0; r < 8; r++) t += red[r][bin];
        red[0][bin] = t;
    }
    __syncthreads();
    if (sub == 0) {
        float a = 0.f;
        for (int b = 0; b <= bin; b++) a += red[0][b];
        out[k * NBIN + bin] = a;
    }
}

extern "C" void kernel_launch(void* const* d_in, const int* in_sizes, int n_in,
                              void* d_out, int out_size) {
    const float* x    = (const float*)d_in[0];
    const float* dirs = (const float*)d_in[1];
    float* out = (float*)d_out;

    pad_kernel<<<(NXP + 255) / 256, 256>>>(x);
    main_kernel<<<dim3(NTILE, ISEG, NGRP), TPB>>>(dirs);
    finalize<<<NDIR, 520>>>(out);
}

// round 6
// speedup vs baseline: 3.4541x; 1.0490x over previous
#include <cuda_runtime.h>

#define NDIR   64
#define NBIN   65
#define INV_DH 0.28867513459481287f    // 1/(2*sqrt(3))
#define D_PER  4
#define NGRP   (NDIR / D_PER)          // 16
#define TPB    128
#define NTILE  32
#define ISEG   4
#define ILEN   16
#define NSLOT  (NTILE * ISEG)          // 128 partials per direction
#define SBIN   65
#define NX     262144
#define XPAD   4224
#define NXP    (NX + XPAD)
#define BIGM   1.0e30f

__device__ float g_part[NDIR * NSLOT * SBIN];
__device__ float g_xp[NXP];

__global__ void pad_kernel(const float* __restrict__ x) {
    int t = blockIdx.x * blockDim.x + threadIdx.x;  // float4 index
    if (t * 4 < NXP) {
        float4 v;
        if (t * 4 + 3 < NX) {
            v = reinterpret_cast<const float4*>(x)[t];
        } else {
            v.x = (t*4+0 < NX) ? x[t*4+0] : 0.f;
            v.y = (t*4+1 < NX) ? x[t*4+1] : 0.f;
            v.z = (t*4+2 < NX) ? x[t*4+2] : 0.f;
            v.w = (t*4+3 < NX) ? x[t*4+3] : 0.f;
        }
        reinterpret_cast<float4*>(g_xp)[t] = v;
    }
}

__device__ __forceinline__ float satfma(float a, float b, float c) {
    float r;
    asm("fma.rn.sat.f32 %0, %1, %2, %3;" : "=f"(r) : "f"(a), "f"(b), "f"(c));
    return r;
}
// flush accLO to [addr] iff t != prev (setp + predicated red, no BSSY)
#define RED_IF_NE(addr, v, tt, pp) \
    asm volatile("{ .reg .pred p; setp.ne.s32 p, %2, %3;\n\t" \
                 "@p red.shared.add.f32 [%0], %1; }" \
                 :: "r"(addr), "f"(v), "r"(tt), "r"(pp) : "memory")

__device__ __forceinline__ void red_sh(unsigned addr, float v) {
    asm volatile("red.shared.add.f32 [%0], %1;" :: "r"(addr), "f"(v) : "memory");
}

__global__ void __launch_bounds__(TPB) main_kernel(const float* __restrict__ dirs) {
    const int g   = blockIdx.z;
    const int seg = blockIdx.y;
    const int tid = threadIdx.x;
    __shared__ float sh[D_PER][68];          // slot index u in [0,65], padded

    for (int t = tid; t < D_PER * 68; t += TPB) ((float*)sh)[t] = 0.f;
    __syncthreads();

    const int base = blockIdx.x * TPB + tid;     // (j,l) column
    const int j = base >> 6, l = base & 63;
    const float mj = (j < 63) ? 1.f : 0.f;
    const float ml = (l < 63) ? 1.f : 0.f;
    const float mjl = mj * ml;
    const int i0 = seg * ILEN;

    // Per-direction constants.
    // pos (d0>=0): F = f+1,  t=floor(F)=ceil(f)=b.  accLO->bin t, accHI->bin t+1.
    //              frac=F-t=1-gg.  S1-mask: q>gg <=> frac>1-q: sat(+M*frac+(q-1)*M)
    // neg (d0<0):  F = 64-f, t=floor(F)=64-b.  slot u <-> bin 65-u.
    //              accLO(slot t)->bin b+1 (S1), accHI(slot t+1)->bin b (S0).
    //              frac=gg.  S1-mask: q>frac: sat(-M*frac+q*M)
    float stepF[D_PER], baseF[D_PER], sgn[D_PER], rsel[D_PER];
    float B1[D_PER], B2[D_PER], B3[D_PER], B4[D_PER], B5[D_PER], B6[D_PER], B7[D_PER];
    int prevb[D_PER];
    float accLO[D_PER], accHI[D_PER];
    unsigned row[D_PER];
    #pragma unroll
    for (int d = 0; d < D_PER; d++) {
        int k = g * D_PER + d;
        float d0 = dirs[3*k], d1 = dirs[3*k+1], d2 = dirs[3*k+2];
        float p0 = fmaxf(d0, 0.f), p1 = fmaxf(d1, 0.f), p2 = fmaxf(d2, 0.f);
        float q1 = p0*INV_DH, q2 = p1*INV_DH, q3 = p2*INV_DH;
        float q4 = (p1+p2)*INV_DH, q5 = (p0+p2)*INV_DH;
        float q6 = (p0+p1)*INV_DH, q7 = (p0+p1+p2)*INV_DH;
        float f00 = fmaf(d1*INV_DH, (float)j, fmaf(d2*INV_DH, (float)l, 32.0f));
        f00 = fmaf(d0*INV_DH, (float)i0, f00);   // f at ii=0
        bool rev = (d0 < 0.f);
        if (!rev) {
            stepF[d] = d0*INV_DH;  baseF[d] = f00 + 1.0f;
            sgn[d] = BIGM;  rsel[d] = 0.f;
            B1[d]=(q1-1.f)*BIGM; B2[d]=(q2-1.f)*BIGM; B3[d]=(q3-1.f)*BIGM;
            B4[d]=(q4-1.f)*BIGM; B5[d]=(q5-1.f)*BIGM; B6[d]=(q6-1.f)*BIGM;
            B7[d]=(q7-1.f)*BIGM;
        } else {
            stepF[d] = -d0*INV_DH; baseF[d] = 64.0f - f00;
            sgn[d] = -BIGM; rsel[d] = 1.f;
            B1[d]=q1*BIGM; B2[d]=q2*BIGM; B3[d]=q3*BIGM;
            B4[d]=q4*BIGM; B5[d]=q5*BIGM; B6[d]=q6*BIGM; B7[d]=q7*BIGM;
        }
        prevb[d] = (int)floorf(baseF[d]);
        accLO[d] = 0.f; accHI[d] = 0.f;
        row[d] = (unsigned)__cvta_generic_to_shared(&sh[d][0]);
    }

    int idx = i0 * 4096 + base;
    float c00 = g_xp[idx];
    float c01 = g_xp[idx + 1];
    float c10 = g_xp[idx + 64];
    float c11 = g_xp[idx + 65];

    #pragma unroll 4
    for (int ii = 0; ii < ILEN; ii++) {
        const float mi = ((i0 + ii) < 63) ? 1.f : 0.f;
        const int nidx = idx + 4096;
        float n00 = g_xp[nidx];
        float n01 = g_xp[nidx + 1];
        float n10 = g_xp[nidx + 64];
        float n11 = g_xp[nidx + 65];

        float m_i   = fmaxf(c00, n00);
        float mc    = fmaxf(fmaxf(c00, c01), fmaxf(c10, c11));
        float v_ei  = -m_i * mi;
        float v_ej  = -fmaxf(c00, c10) * mj;
        float v_el  = -fmaxf(c00, c01) * ml;
        float v_fjl = mc * mjl;
        float v_fil = fmaxf(m_i, fmaxf(c01, n01)) * (mi * ml);
        float v_fij = fmaxf(m_i, fmaxf(c10, n10)) * (mi * mj);
        float v_c   = -fmaxf(mc, fmaxf(fmaxf(n00, n01), fmaxf(n10, n11))) * (mi * mjl);
        float T = ((c00 + v_ei) + (v_ej + v_el)) + ((v_fjl + v_fil) + (v_fij + v_c));
        float fi = (float)ii;

        #pragma unroll
        for (int d = 0; d < D_PER; d++) {
            float F  = fmaf(stepF[d], fi, baseF[d]);
            float tf = floorf(F);
            int   t  = (int)tf;
            float fr = F - tf;

            float m1 = satfma(sgn[d], fr, B1[d]);
            float m2 = satfma(sgn[d], fr, B2[d]);
            float m3 = satfma(sgn[d], fr, B3[d]);
            float m4 = satfma(sgn[d], fr, B4[d]);
            float m5 = satfma(sgn[d], fr, B5[d]);
            float m6 = satfma(sgn[d], fr, B6[d]);
            float m7 = satfma(sgn[d], fr, B7[d]);

            float Sa = fmaf(m1, v_ei, fmaf(m3, v_el, fmaf(m5, v_fil, m7 * v_c)));
            float Sb = fmaf(m2, v_ej, fmaf(m4, v_fjl, m6 * v_fij));
            float S1 = Sa + Sb;
            float S0 = T - S1;
            float dd = S1 - S0;
            float cLO = fmaf(rsel[d], dd, S0);   // pos: S0, neg: S1
            float cHI = T - cLO;

            RED_IF_NE(row[d] + ((unsigned)prevb[d] << 2), accLO[d], t, prevb[d]);
            bool adv = (t != prevb[d]);
            float nLO = adv ? accHI[d] : accLO[d];
            float nHI = adv ? 0.f : accHI[d];
            accLO[d] = nLO + cLO;
            accHI[d] = nHI + cHI;
            prevb[d] = t;
        }

        c00 = n00; c01 = n01; c10 = n10; c11 = n11;
        idx = nidx;
    }

    #pragma unroll
    for (int d = 0; d < D_PER; d++) {
        red_sh(row[d] + ((unsigned)prevb[d] << 2),       accLO[d]);
        red_sh(row[d] + ((unsigned)(prevb[d] + 1) << 2), accHI[d]);
    }
    __syncthreads();

    // Writeout: gather slot u for each real bin (pos: u=bin; neg: u=65-bin)
    const int slot = blockIdx.x * ISEG + seg;
    for (int t = tid; t < D_PER * SBIN; t += TPB) {
        int d = t / SBIN, bin = t - d * SBIN;
        int k = g * D_PER + d;
        bool rev = (dirs[3*k] < 0.f);
        int u = rev ? (65 - bin) : bin;
        g_part[(k * NSLOT + slot) * SBIN + bin] = sh[d][u];
    }
}

// One block per direction; 8 groups of 65 threads reduce 16 slots each.
__global__ void __launch_bounds__(520) finalize(float* __restrict__ out) {
    const int k   = blockIdx.x;
    const int tid = threadIdx.x;
    const int sub = tid / NBIN;
    const int bin = tid - sub * NBIN;
    __shared__ float red[8][NBIN];

    float acc = 0.f;
    const float* p = &g_part[k * NSLOT * SBIN + bin];
    #pragma unroll
    for (int s = 0; s < NSLOT / 8; s++)
        acc += p[(sub * (NSLOT / 8) + s) * SBIN];
    red[sub][bin] = acc;
    __syncthreads();

    if (sub == 0) {
        float t = 0.f;
        #pragma unroll
        for (int r = 0; r < 8; r++) t += red[r][bin];
        red[0][bin] = t;
    }
    __syncthreads();
    if (sub == 0) {
        float a = 0.f;
        for (int b = 0; b <= bin; b++) a += red[0][b];
        out[k * NBIN + bin] = a;
    }
}

extern "C" void kernel_launch(void* const* d_in, const int* in_sizes, int n_in,
                              void* d_out, int out_size) {
    const float* x    = (const float*)d_in[0];
    const float* dirs = (const float*)d_in[1];
    float* out = (float*)d_out;

    pad_kernel<<<(NXP / 4 + 255) / 256, 256>>>(x);
    main_kernel<<<dim3(NTILE, ISEG, NGRP), TPB>>>(dirs);
    finalize<<<NDIR, 520>>>(out);
}